// round 2
// baseline (speedup 1.0000x reference)
#include <cuda_runtime.h>
#include <cstdint>
#include <cstddef>

#define BATCH 64
#define TLEN  1024
#define EDIM  512
#define HDIM  256
#define NROWS (BATCH*TLEN)   /* 65536 */

// ---------------- scratch (device globals: allocation-free rule) ----------------
__device__ float g_x  [(size_t)NROWS * EDIM];  // layer activations (reused across stages)
__device__ float g_xp [(size_t)NROWS * EDIM];  // input-projection results
__device__ float g_hxp[(size_t)NROWS * 16];    // head projections (13 used, padded to 16)

// ---------------- packed f32x2 helpers ----------------
__device__ __forceinline__ unsigned long long pack2(float lo, float hi) {
    unsigned long long r;
    asm("mov.b64 %0, {%1,%2};" : "=l"(r) : "f"(lo), "f"(hi));
    return r;
}
__device__ __forceinline__ float2 unpack2(unsigned long long v) {
    float2 r;
    asm("mov.b64 {%0,%1}, %2;" : "=f"(r.x), "=f"(r.y) : "l"(v));
    return r;
}
__device__ __forceinline__ void fma2(unsigned long long &d, unsigned long long a, unsigned long long b) {
    asm("fma.rn.f32x2 %0, %1, %2, %0;" : "+l"(d) : "l"(a), "l"(b));
}

// ---------------- 1) embedding gather ----------------
__global__ __launch_bounds__(256) void gather_kernel(
    const int* __restrict__ tok, const float* __restrict__ emb, float* __restrict__ x)
{
    int id  = blockIdx.x * 256 + threadIdx.x;   // one float4 per thread
    int row = id >> 7;                          // 128 float4 per row (512 floats)
    int col = id & 127;
    int t   = tok[row];
    reinterpret_cast<float4*>(x)[(size_t)row * 128 + col] =
        reinterpret_cast<const float4*>(emb)[(size_t)t * 128 + col];
}

// ---------------- 2) SGEMM: C[M,512] = A[M,512] * Bw[512,512]^T + bias1 + bias2 ----------------
// Bw is [N][K] row-major (the RNN w_ih layout). 128x128x16 tiles, 256 threads, 8x8/thread, f32x2.
__global__ __launch_bounds__(256, 2) void sgemm512(
    const float* __restrict__ A, const float* __restrict__ Bw,
    const float* __restrict__ bias1, const float* __restrict__ bias2,
    float* __restrict__ C)
{
    const int K = 512, N = 512;
    __shared__ float As[16 * 132];
    __shared__ float Bs[16 * 132];

    int tid = threadIdx.x;
    int m0 = blockIdx.y * 128, n0 = blockIdx.x * 128;

    int lr = tid >> 2;          // 0..63
    int lc = (tid & 3) * 4;     // k offset in {0,4,8,12}
    const float* Ap = A  + (size_t)(m0 + lr) * K + lc;
    const float* Bp = Bw + (size_t)(n0 + lr) * K + lc;

    float4 a0 = *(const float4*)Ap;
    float4 a1 = *(const float4*)(Ap + (size_t)64 * K);
    float4 b0 = *(const float4*)Bp;
    float4 b1 = *(const float4*)(Bp + (size_t)64 * K);

    int tx = tid & 15, ty = tid >> 4;

    unsigned long long acc[8][4];
#pragma unroll
    for (int i = 0; i < 8; i++)
#pragma unroll
        for (int j = 0; j < 4; j++) acc[i][j] = 0ULL;

    for (int kb = 0; kb < 32; kb++) {
        // stage current tile
        As[(lc+0)*132 + lr]      = a0.x; As[(lc+1)*132 + lr]      = a0.y;
        As[(lc+2)*132 + lr]      = a0.z; As[(lc+3)*132 + lr]      = a0.w;
        As[(lc+0)*132 + lr + 64] = a1.x; As[(lc+1)*132 + lr + 64] = a1.y;
        As[(lc+2)*132 + lr + 64] = a1.z; As[(lc+3)*132 + lr + 64] = a1.w;
        Bs[(lc+0)*132 + lr]      = b0.x; Bs[(lc+1)*132 + lr]      = b0.y;
        Bs[(lc+2)*132 + lr]      = b0.z; Bs[(lc+3)*132 + lr]      = b0.w;
        Bs[(lc+0)*132 + lr + 64] = b1.x; Bs[(lc+1)*132 + lr + 64] = b1.y;
        Bs[(lc+2)*132 + lr + 64] = b1.z; Bs[(lc+3)*132 + lr + 64] = b1.w;
        __syncthreads();

        if (kb < 31) {  // prefetch next k-block while computing
            Ap += 16; Bp += 16;
            a0 = *(const float4*)Ap;
            a1 = *(const float4*)(Ap + (size_t)64 * K);
            b0 = *(const float4*)Bp;
            b1 = *(const float4*)(Bp + (size_t)64 * K);
        }

#pragma unroll
        for (int kk = 0; kk < 16; kk++) {
            float4 af0 = *(const float4*)&As[kk*132 + ty*8];
            float4 af1 = *(const float4*)&As[kk*132 + ty*8 + 4];
            ulonglong2 bf0 = *(const ulonglong2*)&Bs[kk*132 + tx*8];
            ulonglong2 bf1 = *(const ulonglong2*)&Bs[kk*132 + tx*8 + 4];
            float am[8] = {af0.x, af0.y, af0.z, af0.w, af1.x, af1.y, af1.z, af1.w};
#pragma unroll
            for (int i = 0; i < 8; i++) {
                unsigned long long ad = pack2(am[i], am[i]);
                fma2(acc[i][0], ad, bf0.x);
                fma2(acc[i][1], ad, bf0.y);
                fma2(acc[i][2], ad, bf1.x);
                fma2(acc[i][3], ad, bf1.y);
            }
        }
        __syncthreads();
    }

    // epilogue: +bias, store
    int n = n0 + tx * 8;
    float bv[8];
#pragma unroll
    for (int j = 0; j < 8; j++) bv[j] = bias1[n + j] + bias2[n + j];

#pragma unroll
    for (int i = 0; i < 8; i++) {
        int m = m0 + ty * 8 + i;
        float2 p0 = unpack2(acc[i][0]);
        float2 p1 = unpack2(acc[i][1]);
        float2 p2 = unpack2(acc[i][2]);
        float2 p3 = unpack2(acc[i][3]);
        float4 o0 = make_float4(p0.x + bv[0], p0.y + bv[1], p1.x + bv[2], p1.y + bv[3]);
        float4 o1 = make_float4(p2.x + bv[4], p2.y + bv[5], p3.x + bv[6], p3.y + bv[7]);
        *(float4*)&C[(size_t)m * N + n]     = o0;
        *(float4*)&C[(size_t)m * N + n + 4] = o1;
    }
}

// ---------------- 3) recurrent layer: one CTA per (dir, batch) ----------------
// h_t = tanh(xp_t + W_hh @ h_{t-1}).
// 512 threads: s = tid>>6 selects contiguous k-slice [32s, 32s+32); g = tid&63 gives
// 4 outputs j = 4g..4g+3. Within a slice: k-rows 0..19 live in REGISTERS (80 floats
// per thread, 160KB RF total), rows 20..31 in SMEM (96KB -> 768 crossbar cyc/step).
// h is stored as duplicated f32 pairs so LDS.128 yields 2 ready FFMA2 operands.
#define RNN_W_SM_ROWS   12                    /* smem k-rows per slice   */
#define RNN_W_REG_ROWS  20                    /* register k-rows per slice */
#define RNN_SMEM_FLOATS (96*256 + 512 + 8*264)
#define RNN_SMEM_BYTES  (RNN_SMEM_FLOATS * 4)

__global__ __launch_bounds__(512, 1) void rnn_layer(
    const float* __restrict__ xp,    // [B*T, 512]; (b*T+t)*512 + dir*256 + j
    const float* __restrict__ Whh_l, // layer base: [2, 256, 256]
    float* __restrict__ xout,        // [B*T, 512]
    int apply_relu)
{
    extern __shared__ float sm[];
    float*              Wsm = sm;                                   // [96][256]: row = s*12+m, col = j
    unsigned long long* h2  = (unsigned long long*)(sm + 96*256);   // duplicated h pairs, [256] (idx k)
    float*              P   = sm + 96*256 + 512;                    // partials [8][264]

    const int tid = threadIdx.x;
    const int dir = blockIdx.x >> 6;
    const int b   = blockIdx.x & 63;
    const float* W = Whh_l + (size_t)dir * HDIM * HDIM;   // [j][k] row-major

    // Fill smem W: Wsm[(s2*12 + m)*256 + j] = W[j][32*s2 + 20 + m], m = 0..11.
    // Iterate (j, s2, q) with q indexing 3 float4 chunks of the 12-float tail.
    for (int idx = tid; idx < 256 * 8 * 3; idx += 512) {
        int q  = idx % 3;
        int s2 = (idx / 3) & 7;
        int j  = idx / 24;
        float4 w = *(const float4*)&W[(size_t)j * HDIM + 32 * s2 + 20 + 4 * q];
        int m = 4 * q;
        Wsm[(s2*12 + m + 0)*HDIM + j] = w.x;
        Wsm[(s2*12 + m + 1)*HDIM + j] = w.y;
        Wsm[(s2*12 + m + 2)*HDIM + j] = w.z;
        Wsm[(s2*12 + m + 3)*HDIM + j] = w.w;
    }

    const int s = tid >> 6;   // 0..7
    const int g = tid & 63;   // 0..63
    const int k0 = 32 * s;

    // register W: rows i = 0..19 (k = k0+i), packed as (w[j0],w[j1]) and (w[j2],w[j3])
    unsigned long long wreg[RNN_W_REG_ROWS][2];
#pragma unroll
    for (int i = 0; i < RNN_W_REG_ROWS; i++) {
        int k = k0 + i;
        float w0 = W[(size_t)(4*g+0) * HDIM + k];
        float w1 = W[(size_t)(4*g+1) * HDIM + k];
        float w2 = W[(size_t)(4*g+2) * HDIM + k];
        float w3 = W[(size_t)(4*g+3) * HDIM + k];
        wreg[i][0] = pack2(w0, w1);
        wreg[i][1] = pack2(w2, w3);
    }

    if (tid < HDIM) h2[tid] = 0ULL;
    __syncthreads();

    const float* xpb = xp   + (size_t)b * TLEN * EDIM + dir * HDIM;
    float*       xob = xout + (size_t)b * TLEN * EDIM + dir * HDIM;
    const int t0 = dir ? (TLEN - 1) : 0;
    const int dt = dir ? -1 : 1;

    float xp_cur = (tid < HDIM) ? xpb[(size_t)t0 * EDIM + tid] : 0.f;

    const float* Wrow = Wsm + (s * RNN_W_SM_ROWS) * HDIM + 4 * g;
    const unsigned long long* h2p = h2 + k0;

    int t = t0;
    for (int step = 0; step < TLEN; step++) {
        unsigned long long acc0 = 0ULL, acc1 = 0ULL;
        // register part: k = k0 .. k0+19 (10 x LDS.128 broadcast h-pair loads)
#pragma unroll
        for (int i2 = 0; i2 < RNN_W_REG_ROWS / 2; i2++) {
            ulonglong2 hp = *(const ulonglong2*)(h2p + 2 * i2);
            fma2(acc0, wreg[2*i2+0][0], hp.x);
            fma2(acc1, wreg[2*i2+0][1], hp.x);
            fma2(acc0, wreg[2*i2+1][0], hp.y);
            fma2(acc1, wreg[2*i2+1][1], hp.y);
        }
        // smem part: k = k0+20 .. k0+31 (6 h-pair loads + 12 LDS.128 W loads)
#pragma unroll
        for (int m2 = 0; m2 < RNN_W_SM_ROWS / 2; m2++) {
            ulonglong2 hp = *(const ulonglong2*)(h2p + 20 + 2 * m2);
            ulonglong2 w0 = *(const ulonglong2*)(Wrow + (2*m2+0) * HDIM);
            ulonglong2 w1 = *(const ulonglong2*)(Wrow + (2*m2+1) * HDIM);
            fma2(acc0, w0.x, hp.x);
            fma2(acc1, w0.y, hp.x);
            fma2(acc0, w1.x, hp.y);
            fma2(acc1, w1.y, hp.y);
        }
        float2 u0 = unpack2(acc0);
        float2 u1 = unpack2(acc1);
        *(float4*)&P[s * 264 + 4 * g] = make_float4(u0.x, u0.y, u1.x, u1.y);
        __syncthreads();

        if (tid < HDIM) {
            float ssum = 0.f;
#pragma unroll
            for (int s2 = 0; s2 < 8; s2++) ssum += P[s2 * 264 + tid];
            float pre = ssum + xp_cur;
            if (step + 1 < TLEN)  // prefetch next step's xp (hidden behind tanh + barrier)
                xp_cur = xpb[(size_t)(t + dt) * EDIM + tid];
            float hv = tanhf(pre);
            h2[tid] = pack2(hv, hv);
            xob[(size_t)t * EDIM + tid] = apply_relu ? fmaxf(hv, 0.f) : hv;
        }
        __syncthreads();
        t += dt;
    }
}

// ---------------- 4) head input projection: hxp[row, 0..12] = relu_x[row,:] @ Wh^T + b ----------------
__global__ __launch_bounds__(256) void head_proj(
    const float* __restrict__ x,
    const float* __restrict__ wi, const float* __restrict__ wf, const float* __restrict__ wc,
    const float* __restrict__ bii, const float* __restrict__ bhi,
    const float* __restrict__ bif, const float* __restrict__ bhf,
    const float* __restrict__ bic, const float* __restrict__ bhc,
    float* __restrict__ hxp)
{
    __shared__ float xs[16 * 516];
    int tid = threadIdx.x;
    int row0 = blockIdx.x * 16;

    for (int i = tid; i < 16 * 128; i += 256) {
        int r = i >> 7, c = i & 127;
        float4 v = reinterpret_cast<const float4*>(x + (size_t)(row0 + r) * 512)[c];
        *(float4*)&xs[r * 516 + c * 4] = v;
    }
    __syncthreads();

    int r = tid >> 4, c = tid & 15;
    if (c < 13) {
        const float* w;
        float bias;
        if (c < 3)      { w = wi + (size_t)c * 512;        bias = bii[c]     + bhi[c];     }
        else if (c < 8) { w = wf + (size_t)(c - 3) * 512;  bias = bif[c - 3] + bhf[c - 3]; }
        else            { w = wc + (size_t)(c - 8) * 512;  bias = bic[c - 8] + bhc[c - 8]; }
        float sum = 0.f;
        const float* xr = &xs[r * 516];
#pragma unroll 8
        for (int k = 0; k < 512; k += 4) {
            float4 wv = *(const float4*)&w[k];
            sum += xr[k] * wv.x + xr[k+1] * wv.y + xr[k+2] * wv.z + xr[k+3] * wv.w;
        }
        hxp[(size_t)(row0 + r) * 16 + c] = sum + bias;
    }
}

// ---------------- 5) head recurrences: one warp per (batch, head), lanes = channels ----------------
__global__ __launch_bounds__(256) void head_rnn(
    const float* __restrict__ hxp,
    const float* __restrict__ whi, const float* __restrict__ whf, const float* __restrict__ whc,
    float* __restrict__ out)
{
    int wg   = (blockIdx.x * 256 + threadIdx.x) >> 5;   // 0..191
    int lane = threadIdx.x & 31;
    if (wg >= BATCH * 3) return;
    int b = wg / 3, head = wg - 3 * b;

    int C    = (head == 0) ? 3 : 5;
    int coff = (head == 0) ? 0 : ((head == 1) ? 3 : 8);
    const float* whh = (head == 0) ? whi : ((head == 1) ? whf : whc);
    size_t ooff = (head == 0) ? 0
                : ((head == 1) ? (size_t)NROWS * 3 : (size_t)NROWS * 8);

    float wr[5] = {0.f, 0.f, 0.f, 0.f, 0.f};
    if (lane < C) {
#pragma unroll
        for (int j = 0; j < 5; j++) if (j < C) wr[j] = whh[lane * C + j];
    }

    int xoffs = (lane < C) ? (coff + lane) : 0;   // keep OOB lanes in-bounds
    const float* xb = hxp + (size_t)b * TLEN * 16 + xoffs;
    float*       ob = out + ooff + (size_t)b * TLEN * C + lane;

    float hv = 0.f;
    float Acur[8], Anxt[8];
#pragma unroll
    for (int i = 0; i < 8; i++) Acur[i] = xb[(size_t)i * 16];

    for (int tb = 0; tb < TLEN; tb += 8) {
        bool more = (tb + 8) < TLEN;
#pragma unroll
        for (int i = 0; i < 8; i++)
            Anxt[i] = more ? xb[(size_t)(tb + 8 + i) * 16] : 0.f;

#pragma unroll
        for (int i = 0; i < 8; i++) {
            float sum = Acur[i];
#pragma unroll
            for (int j = 0; j < 5; j++) {
                float hj = __shfl_sync(0xffffffffu, hv, j);
                sum += wr[j] * hj;   // wr[j]=0 for j>=C
            }
            hv = tanhf(sum);
            if (lane < C) ob[(size_t)(tb + i) * C] = hv;
        }
#pragma unroll
        for (int i = 0; i < 8; i++) Acur[i] = Anxt[i];
    }
}

// ---------------- launch ----------------
extern "C" void kernel_launch(void* const* d_in, const int* in_sizes, int n_in,
                              void* d_out, int out_size)
{
    const int*   tokens = (const int*)  d_in[0];
    const float* emb    = (const float*)d_in[1];
    const float* w_ih   = (const float*)d_in[2];   // [2,2,256,512]
    const float* w_hh   = (const float*)d_in[3];   // [2,2,256,256]
    const float* b_ih   = (const float*)d_in[4];   // [2,2,256]
    const float* b_hh   = (const float*)d_in[5];
    const float* iwi = (const float*)d_in[6];
    const float* iwh = (const float*)d_in[7];
    const float* ibi = (const float*)d_in[8];
    const float* ibh = (const float*)d_in[9];
    const float* fwi = (const float*)d_in[10];
    const float* fwh = (const float*)d_in[11];
    const float* fbi = (const float*)d_in[12];
    const float* fbh = (const float*)d_in[13];
    const float* cwi = (const float*)d_in[14];
    const float* cwh = (const float*)d_in[15];
    const float* cbi = (const float*)d_in[16];
    const float* cbh = (const float*)d_in[17];
    float* out = (float*)d_out;

    float *px, *pxp, *phxp;
    cudaGetSymbolAddress((void**)&px,   g_x);
    cudaGetSymbolAddress((void**)&pxp,  g_xp);
    cudaGetSymbolAddress((void**)&phxp, g_hxp);

    cudaFuncSetAttribute(rnn_layer, cudaFuncAttributeMaxDynamicSharedMemorySize, RNN_SMEM_BYTES);

    // 1) embedding gather
    gather_kernel<<<(NROWS * 128) / 256, 256>>>(tokens, emb, px);

    dim3 ggrid(512 / 128, NROWS / 128);

    // 2) layer 0: projection + recurrence (writes back into g_x)
    sgemm512<<<ggrid, 256>>>(px, w_ih, b_ih, b_hh, pxp);
    rnn_layer<<<128, 512, RNN_SMEM_BYTES>>>(pxp, w_hh, px, 0);

    // 3) layer 1 (relu applied at the recurrence output)
    sgemm512<<<ggrid, 256>>>(px, w_ih + (size_t)2 * HDIM * EDIM,
                             b_ih + 2 * HDIM, b_hh + 2 * HDIM, pxp);
    rnn_layer<<<128, 512, RNN_SMEM_BYTES>>>(pxp, w_hh + (size_t)2 * HDIM * HDIM, px, 1);

    // 4) heads
    head_proj<<<NROWS / 16, 256>>>(px, iwi, fwi, cwi, ibi, ibh, fbi, fbh, cbi, cbh, phxp);
    head_rnn<<<24, 256>>>(phxp, iwh, fwh, cwh, out);
}

// round 4
// speedup vs baseline: 1.0683x; 1.0683x over previous
#include <cuda_runtime.h>
#include <cstdint>
#include <cstddef>

#define BATCH 64
#define TLEN  1024
#define EDIM  512
#define HDIM  256
#define NROWS (BATCH*TLEN)   /* 65536 */

// ---------------- scratch (device globals: allocation-free rule) ----------------
__device__ float g_x  [(size_t)NROWS * EDIM];  // layer activations (reused across stages)
__device__ float g_xp [(size_t)NROWS * EDIM];  // input-projection results
__device__ float g_hxp[(size_t)NROWS * 16];    // head projections (13 used, padded to 16)

// ---------------- packed f32x2 helpers ----------------
__device__ __forceinline__ unsigned long long pack2(float lo, float hi) {
    unsigned long long r;
    asm("mov.b64 %0, {%1,%2};" : "=l"(r) : "f"(lo), "f"(hi));
    return r;
}
__device__ __forceinline__ float2 unpack2(unsigned long long v) {
    float2 r;
    asm("mov.b64 {%0,%1}, %2;" : "=f"(r.x), "=f"(r.y) : "l"(v));
    return r;
}
__device__ __forceinline__ void fma2(unsigned long long &d, unsigned long long a, unsigned long long b) {
    asm("fma.rn.f32x2 %0, %1, %2, %0;" : "+l"(d) : "l"(a), "l"(b));
}

// ---------------- 1) embedding gather ----------------
__global__ __launch_bounds__(256) void gather_kernel(
    const int* __restrict__ tok, const float* __restrict__ emb, float* __restrict__ x)
{
    int id  = blockIdx.x * 256 + threadIdx.x;   // one float4 per thread
    int row = id >> 7;                          // 128 float4 per row (512 floats)
    int col = id & 127;
    int t   = tok[row];
    reinterpret_cast<float4*>(x)[(size_t)row * 128 + col] =
        reinterpret_cast<const float4*>(emb)[(size_t)t * 128 + col];
}

// ---------------- 2) SGEMM: C[M,512] = A[M,512] * Bw[512,512]^T + bias1 + bias2 ----------------
// Bw is [N][K] row-major (the RNN w_ih layout). 128x128x16 tiles, 256 threads, 8x8/thread, f32x2.
__global__ __launch_bounds__(256, 2) void sgemm512(
    const float* __restrict__ A, const float* __restrict__ Bw,
    const float* __restrict__ bias1, const float* __restrict__ bias2,
    float* __restrict__ C)
{
    const int K = 512, N = 512;
    __shared__ float As[16 * 132];
    __shared__ float Bs[16 * 132];

    int tid = threadIdx.x;
    int m0 = blockIdx.y * 128, n0 = blockIdx.x * 128;

    int lr = tid >> 2;          // 0..63
    int lc = (tid & 3) * 4;     // k offset in {0,4,8,12}
    const float* Ap = A  + (size_t)(m0 + lr) * K + lc;
    const float* Bp = Bw + (size_t)(n0 + lr) * K + lc;

    float4 a0 = *(const float4*)Ap;
    float4 a1 = *(const float4*)(Ap + (size_t)64 * K);
    float4 b0 = *(const float4*)Bp;
    float4 b1 = *(const float4*)(Bp + (size_t)64 * K);

    int tx = tid & 15, ty = tid >> 4;

    unsigned long long acc[8][4];
#pragma unroll
    for (int i = 0; i < 8; i++)
#pragma unroll
        for (int j = 0; j < 4; j++) acc[i][j] = 0ULL;

    for (int kb = 0; kb < 32; kb++) {
        // stage current tile
        As[(lc+0)*132 + lr]      = a0.x; As[(lc+1)*132 + lr]      = a0.y;
        As[(lc+2)*132 + lr]      = a0.z; As[(lc+3)*132 + lr]      = a0.w;
        As[(lc+0)*132 + lr + 64] = a1.x; As[(lc+1)*132 + lr + 64] = a1.y;
        As[(lc+2)*132 + lr + 64] = a1.z; As[(lc+3)*132 + lr + 64] = a1.w;
        Bs[(lc+0)*132 + lr]      = b0.x; Bs[(lc+1)*132 + lr]      = b0.y;
        Bs[(lc+2)*132 + lr]      = b0.z; Bs[(lc+3)*132 + lr]      = b0.w;
        Bs[(lc+0)*132 + lr + 64] = b1.x; Bs[(lc+1)*132 + lr + 64] = b1.y;
        Bs[(lc+2)*132 + lr + 64] = b1.z; Bs[(lc+3)*132 + lr + 64] = b1.w;
        __syncthreads();

        if (kb < 31) {  // prefetch next k-block while computing
            Ap += 16; Bp += 16;
            a0 = *(const float4*)Ap;
            a1 = *(const float4*)(Ap + (size_t)64 * K);
            b0 = *(const float4*)Bp;
            b1 = *(const float4*)(Bp + (size_t)64 * K);
        }

#pragma unroll
        for (int kk = 0; kk < 16; kk++) {
            float4 af0 = *(const float4*)&As[kk*132 + ty*8];
            float4 af1 = *(const float4*)&As[kk*132 + ty*8 + 4];
            ulonglong2 bf0 = *(const ulonglong2*)&Bs[kk*132 + tx*8];
            ulonglong2 bf1 = *(const ulonglong2*)&Bs[kk*132 + tx*8 + 4];
            float am[8] = {af0.x, af0.y, af0.z, af0.w, af1.x, af1.y, af1.z, af1.w};
#pragma unroll
            for (int i = 0; i < 8; i++) {
                unsigned long long ad = pack2(am[i], am[i]);
                fma2(acc[i][0], ad, bf0.x);
                fma2(acc[i][1], ad, bf0.y);
                fma2(acc[i][2], ad, bf1.x);
                fma2(acc[i][3], ad, bf1.y);
            }
        }
        __syncthreads();
    }

    // epilogue: +bias, store
    int n = n0 + tx * 8;
    float bv[8];
#pragma unroll
    for (int j = 0; j < 8; j++) bv[j] = bias1[n + j] + bias2[n + j];

#pragma unroll
    for (int i = 0; i < 8; i++) {
        int m = m0 + ty * 8 + i;
        float2 p0 = unpack2(acc[i][0]);
        float2 p1 = unpack2(acc[i][1]);
        float2 p2 = unpack2(acc[i][2]);
        float2 p3 = unpack2(acc[i][3]);
        float4 o0 = make_float4(p0.x + bv[0], p0.y + bv[1], p1.x + bv[2], p1.y + bv[3]);
        float4 o1 = make_float4(p2.x + bv[4], p2.y + bv[5], p3.x + bv[6], p3.y + bv[7]);
        *(float4*)&C[(size_t)m * N + n]     = o0;
        *(float4*)&C[(size_t)m * N + n + 4] = o1;
    }
}

// ---------------- 3) recurrent layer: one CTA per (dir, batch) ----------------
// h_t = tanh(xp_t + W_hh @ h_{t-1}).
// 512 threads: s = tid>>6 is a contiguous k-slice [32s,32s+32); g = tid&63 gives 4
// outputs j = 4g..4g+3. FMA pairs are packed along k (h stored PLAIN, no duplication):
// acc[jj] accumulates (w[j,2p]*h[2p], w[j,2p+1]*h[2p+1]); horizontal add at the end.
// Per slice: k-rows 0..23 in REGISTERS (96 W floats/thread), rows 24..31 thread-private
// in SMEM (64KB total -> 512 crossbar cyc/step). h broadcasts: 8x LDS.128 per thread.
#define RNN_SMEM_FLOATS (512*32 + 256 + 8*264)
#define RNN_SMEM_BYTES  (RNN_SMEM_FLOATS * 4)

__global__ __launch_bounds__(512, 1) void rnn_layer(
    const float* __restrict__ xp,    // [B*T, 512]; (b*T+t)*512 + dir*256 + j
    const float* __restrict__ Whh_l, // layer base: [2, 256, 256]
    float* __restrict__ xout,        // [B*T, 512]
    int apply_relu)
{
    extern __shared__ float sm[];
    float* Wsm = sm;                  // 512 threads x 32 floats, thread-private chunks
    float* hsm = sm + 512 * 32;       // plain h [256]
    float* P   = sm + 512 * 32 + 256; // partials [8][264]

    const int tid  = threadIdx.x;
    const int wid  = tid >> 5;
    const int lane = tid & 31;
    const int dir  = blockIdx.x >> 6;
    const int b    = blockIdx.x & 63;
    const float* W = Whh_l + (size_t)dir * HDIM * HDIM;   // [j][k] row-major

    const int s = tid >> 6;   // 0..7
    const int g = tid & 63;   // 0..63
    const int k0 = 32 * s;

    // ---- fill thread-private smem W: chunks cc=0..7 -> jj=cc>>1, krel base 24+4*(cc&1)
    float4* WsmV = (float4*)Wsm;
#pragma unroll
    for (int cc = 0; cc < 8; cc++) {
        int jj = cc >> 1;
        int kb = 24 + 4 * (cc & 1);
        float4 w = *(const float4*)&W[(size_t)(4*g + jj) * HDIM + k0 + kb];
        WsmV[(wid * 8 + cc) * 32 + lane] = w;
    }

    // ---- register W: k-pairs p=0..11 (krel 0..23) for 4 outputs
    unsigned long long wreg[12][4];
#pragma unroll
    for (int p = 0; p < 12; p++) {
#pragma unroll
        for (int jj = 0; jj < 4; jj++) {
            float2 w = *(const float2*)&W[(size_t)(4*g + jj) * HDIM + k0 + 2*p];
            wreg[p][jj] = pack2(w.x, w.y);
        }
    }

    if (tid < HDIM) hsm[tid] = 0.f;
    __syncthreads();

    const float* xpb = xp   + (size_t)b * TLEN * EDIM + dir * HDIM;
    float*       xob = xout + (size_t)b * TLEN * EDIM + dir * HDIM;
    const int t0 = dir ? (TLEN - 1) : 0;
    const int dt = dir ? -1 : 1;

    float xp_cur = (tid < HDIM) ? xpb[(size_t)t0 * EDIM + tid] : 0.f;

    const ulonglong2* hp2 = (const ulonglong2*)(hsm + k0);            // 8 x 16B chunks
    const ulonglong2* wsv = (const ulonglong2*)Wsm + (wid * 8) * 32 + lane;

    int t = t0;
    for (int step = 0; step < TLEN; step++) {
        unsigned long long acc0 = 0ULL, acc1 = 0ULL, acc2 = 0ULL, acc3 = 0ULL;

        // register part: krel 0..23 (6 broadcast LDS.128 of h)
#pragma unroll
        for (int c = 0; c < 6; c++) {
            ulonglong2 hp = hp2[c];
            fma2(acc0, wreg[2*c][0], hp.x);
            fma2(acc1, wreg[2*c][1], hp.x);
            fma2(acc2, wreg[2*c][2], hp.x);
            fma2(acc3, wreg[2*c][3], hp.x);
            fma2(acc0, wreg[2*c+1][0], hp.y);
            fma2(acc1, wreg[2*c+1][1], hp.y);
            fma2(acc2, wreg[2*c+1][2], hp.y);
            fma2(acc3, wreg[2*c+1][3], hp.y);
        }
        // smem part: krel 24..31 (2 h chunks + 8 thread-private W LDS.128)
        {
            ulonglong2 hp6 = hp2[6];
            ulonglong2 hp7 = hp2[7];
            ulonglong2 w;
            w = wsv[0*32]; fma2(acc0, w.x, hp6.x); fma2(acc0, w.y, hp6.y);
            w = wsv[1*32]; fma2(acc0, w.x, hp7.x); fma2(acc0, w.y, hp7.y);
            w = wsv[2*32]; fma2(acc1, w.x, hp6.x); fma2(acc1, w.y, hp6.y);
            w = wsv[3*32]; fma2(acc1, w.x, hp7.x); fma2(acc1, w.y, hp7.y);
            w = wsv[4*32]; fma2(acc2, w.x, hp6.x); fma2(acc2, w.y, hp6.y);
            w = wsv[5*32]; fma2(acc2, w.x, hp7.x); fma2(acc2, w.y, hp7.y);
            w = wsv[6*32]; fma2(acc3, w.x, hp6.x); fma2(acc3, w.y, hp6.y);
            w = wsv[7*32]; fma2(acc3, w.x, hp7.x); fma2(acc3, w.y, hp7.y);
        }

        float2 m0 = unpack2(acc0), m1 = unpack2(acc1), m2 = unpack2(acc2), m3 = unpack2(acc3);
        *(float4*)&P[s * 264 + 4 * g] =
            make_float4(m0.x + m0.y, m1.x + m1.y, m2.x + m2.y, m3.x + m3.y);
        __syncthreads();

        if (tid < HDIM) {
            float ssum = 0.f;
#pragma unroll
            for (int s2 = 0; s2 < 8; s2++) ssum += P[s2 * 264 + tid];
            float pre = ssum + xp_cur;
            if (step + 1 < TLEN)  // prefetch next step's xp (hidden behind tanh + barrier)
                xp_cur = xpb[(size_t)(t + dt) * EDIM + tid];
            float hv = tanhf(pre);
            hsm[tid] = hv;
            xob[(size_t)t * EDIM + tid] = apply_relu ? fmaxf(hv, 0.f) : hv;
        }
        __syncthreads();
        t += dt;
    }
}

// ---------------- 4) head input projection: hxp[row, 0..12] = relu_x[row,:] @ Wh^T + b ----------------
__global__ __launch_bounds__(256) void head_proj(
    const float* __restrict__ x,
    const float* __restrict__ wi, const float* __restrict__ wf, const float* __restrict__ wc,
    const float* __restrict__ bii, const float* __restrict__ bhi,
    const float* __restrict__ bif, const float* __restrict__ bhf,
    const float* __restrict__ bic, const float* __restrict__ bhc,
    float* __restrict__ hxp)
{
    __shared__ float xs[16 * 516];
    int tid = threadIdx.x;
    int row0 = blockIdx.x * 16;

    for (int i = tid; i < 16 * 128; i += 256) {
        int r = i >> 7, c = i & 127;
        float4 v = reinterpret_cast<const float4*>(x + (size_t)(row0 + r) * 512)[c];
        *(float4*)&xs[r * 516 + c * 4] = v;
    }
    __syncthreads();

    int r = tid >> 4, c = tid & 15;
    if (c < 13) {
        const float* w;
        float bias;
        if (c < 3)      { w = wi + (size_t)c * 512;        bias = bii[c]     + bhi[c];     }
        else if (c < 8) { w = wf + (size_t)(c - 3) * 512;  bias = bif[c - 3] + bhf[c - 3]; }
        else            { w = wc + (size_t)(c - 8) * 512;  bias = bic[c - 8] + bhc[c - 8]; }
        float sum = 0.f;
        const float* xr = &xs[r * 516];
#pragma unroll 8
        for (int k = 0; k < 512; k += 4) {
            float4 wv = *(const float4*)&w[k];
            sum += xr[k] * wv.x + xr[k+1] * wv.y + xr[k+2] * wv.z + xr[k+3] * wv.w;
        }
        hxp[(size_t)(row0 + r) * 16 + c] = sum + bias;
    }
}

// ---------------- 5) head recurrences: one warp per (batch, head), lanes = channels ----------------
__global__ __launch_bounds__(256) void head_rnn(
    const float* __restrict__ hxp,
    const float* __restrict__ whi, const float* __restrict__ whf, const float* __restrict__ whc,
    float* __restrict__ out)
{
    int wg   = (blockIdx.x * 256 + threadIdx.x) >> 5;   // 0..191
    int lane = threadIdx.x & 31;
    if (wg >= BATCH * 3) return;
    int b = wg / 3, head = wg - 3 * b;

    int C    = (head == 0) ? 3 : 5;
    int coff = (head == 0) ? 0 : ((head == 1) ? 3 : 8);
    const float* whh = (head == 0) ? whi : ((head == 1) ? whf : whc);
    size_t ooff = (head == 0) ? 0
                : ((head == 1) ? (size_t)NROWS * 3 : (size_t)NROWS * 8);

    float wr[5] = {0.f, 0.f, 0.f, 0.f, 0.f};
    if (lane < C) {
#pragma unroll
        for (int j = 0; j < 5; j++) if (j < C) wr[j] = whh[lane * C + j];
    }

    int xoffs = (lane < C) ? (coff + lane) : 0;   // keep OOB lanes in-bounds
    const float* xb = hxp + (size_t)b * TLEN * 16 + xoffs;
    float*       ob = out + ooff + (size_t)b * TLEN * C + lane;

    float hv = 0.f;
    float Acur[8], Anxt[8];
#pragma unroll
    for (int i = 0; i < 8; i++) Acur[i] = xb[(size_t)i * 16];

    for (int tb = 0; tb < TLEN; tb += 8) {
        bool more = (tb + 8) < TLEN;
#pragma unroll
        for (int i = 0; i < 8; i++)
            Anxt[i] = more ? xb[(size_t)(tb + 8 + i) * 16] : 0.f;

#pragma unroll
        for (int i = 0; i < 8; i++) {
            float sum = Acur[i];
#pragma unroll
            for (int j = 0; j < 5; j++) {
                float hj = __shfl_sync(0xffffffffu, hv, j);
                sum += wr[j] * hj;   // wr[j]=0 for j>=C
            }
            hv = tanhf(sum);
            if (lane < C) ob[(size_t)(tb + i) * C] = hv;
        }
#pragma unroll
        for (int i = 0; i < 8; i++) Acur[i] = Anxt[i];
    }
}

// ---------------- launch ----------------
extern "C" void kernel_launch(void* const* d_in, const int* in_sizes, int n_in,
                              void* d_out, int out_size)
{
    const int*   tokens = (const int*)  d_in[0];
    const float* emb    = (const float*)d_in[1];
    const float* w_ih   = (const float*)d_in[2];   // [2,2,256,512]
    const float* w_hh   = (const float*)d_in[3];   // [2,2,256,256]
    const float* b_ih   = (const float*)d_in[4];   // [2,2,256]
    const float* b_hh   = (const float*)d_in[5];
    const float* iwi = (const float*)d_in[6];
    const float* iwh = (const float*)d_in[7];
    const float* ibi = (const float*)d_in[8];
    const float* ibh = (const float*)d_in[9];
    const float* fwi = (const float*)d_in[10];
    const float* fwh = (const float*)d_in[11];
    const float* fbi = (const float*)d_in[12];
    const float* fbh = (const float*)d_in[13];
    const float* cwi = (const float*)d_in[14];
    const float* cwh = (const float*)d_in[15];
    const float* cbi = (const float*)d_in[16];
    const float* cbh = (const float*)d_in[17];
    float* out = (float*)d_out;

    float *px, *pxp, *phxp;
    cudaGetSymbolAddress((void**)&px,   g_x);
    cudaGetSymbolAddress((void**)&pxp,  g_xp);
    cudaGetSymbolAddress((void**)&phxp, g_hxp);

    cudaFuncSetAttribute(rnn_layer, cudaFuncAttributeMaxDynamicSharedMemorySize, RNN_SMEM_BYTES);

    // 1) embedding gather
    gather_kernel<<<(NROWS * 128) / 256, 256>>>(tokens, emb, px);

    dim3 ggrid(512 / 128, NROWS / 128);

    // 2) layer 0: projection + recurrence (writes back into g_x)
    sgemm512<<<ggrid, 256>>>(px, w_ih, b_ih, b_hh, pxp);
    rnn_layer<<<128, 512, RNN_SMEM_BYTES>>>(pxp, w_hh, px, 0);

    // 3) layer 1 (relu applied at the recurrence output)
    sgemm512<<<ggrid, 256>>>(px, w_ih + (size_t)2 * HDIM * EDIM,
                             b_ih + 2 * HDIM, b_hh + 2 * HDIM, pxp);
    rnn_layer<<<128, 512, RNN_SMEM_BYTES>>>(pxp, w_hh + (size_t)2 * HDIM * HDIM, px, 1);

    // 4) heads
    head_proj<<<NROWS / 16, 256>>>(px, iwi, fwi, cwi, ibi, ibh, fbi, fbh, cbi, cbh, phxp);
    head_rnn<<<24, 256>>>(phxp, iwh, fwh, cwh, out);
}

// round 6
// speedup vs baseline: 1.3347x; 1.2494x over previous
#include <cuda_runtime.h>
#include <cuda_bf16.h>
#include <cstdint>
#include <cstddef>

#define BATCH 64
#define TLEN  1024
#define EDIM  512
#define HDIM  256
#define NROWS (BATCH*TLEN)   /* 65536 */

// ---------------- scratch (device globals: allocation-free rule) ----------------
__device__ float          g_x  [(size_t)NROWS * EDIM];  // f32 activations (layer-1 out, head in)
__device__ float          g_xp [(size_t)NROWS * EDIM];  // input-projection results
__device__ float          g_hxp[(size_t)NROWS * 16];    // head projections (13 used)
__device__ __nv_bfloat16  g_ahi[(size_t)NROWS * EDIM];  // A hi (bf16 split of GEMM input)
__device__ __nv_bfloat16  g_alo[(size_t)NROWS * EDIM];  // A lo
__device__ __nv_bfloat16  g_bhi[(size_t)EDIM * EDIM];   // W hi (512x512)
__device__ __nv_bfloat16  g_blo[(size_t)EDIM * EDIM];   // W lo

// ---------------- packed f32x2 helpers ----------------
__device__ __forceinline__ unsigned long long pack2(float lo, float hi) {
    unsigned long long r;
    asm("mov.b64 %0, {%1,%2};" : "=l"(r) : "f"(lo), "f"(hi));
    return r;
}
__device__ __forceinline__ float2 unpack2(unsigned long long v) {
    float2 r;
    asm("mov.b64 {%0,%1}, %2;" : "=f"(r.x), "=f"(r.y) : "l"(v));
    return r;
}
__device__ __forceinline__ void fma2(unsigned long long &d, unsigned long long a, unsigned long long b) {
    asm("fma.rn.f32x2 %0, %1, %2, %0;" : "+l"(d) : "l"(a), "l"(b));
}

// ---------------- small helpers ----------------
__device__ __forceinline__ uint32_t smem_u32(const void* p) {
    uint32_t a;
    asm("{ .reg .u64 t; cvta.to.shared.u64 t, %1; cvt.u32.u64 %0, t; }" : "=r"(a) : "l"(p));
    return a;
}
__device__ __forceinline__ uint32_t lds32(uint32_t a) {
    uint32_t v; asm("ld.shared.b32 %0, [%1];" : "=r"(v) : "r"(a)); return v;
}
__device__ __forceinline__ void cpasync16(uint32_t dst, const void* src) {
    asm volatile("cp.async.cg.shared.global [%0], [%1], 16;" :: "r"(dst), "l"(src));
}
__device__ __forceinline__ void mma16816(float* d, uint32_t a0, uint32_t a1, uint32_t a2,
                                         uint32_t a3, uint32_t b0, uint32_t b1) {
    asm("mma.sync.aligned.m16n8k16.row.col.f32.bf16.bf16.f32 "
        "{%0,%1,%2,%3}, {%4,%5,%6,%7}, {%8,%9}, {%0,%1,%2,%3};"
        : "+f"(d[0]), "+f"(d[1]), "+f"(d[2]), "+f"(d[3])
        : "r"(a0), "r"(a1), "r"(a2), "r"(a3), "r"(b0), "r"(b1));
}
__device__ __forceinline__ uint32_t pkbf2(__nv_bfloat16 a, __nv_bfloat16 b) {
    __nv_bfloat162 t = __halves2bfloat162(a, b);
    return *reinterpret_cast<uint32_t*>(&t);
}
// split float4 -> 4 hi bf16 (uint2) + 4 lo bf16 (uint2)
__device__ __forceinline__ void split4(float4 v, uint2& H, uint2& L) {
    __nv_bfloat16 h0 = __float2bfloat16_rn(v.x), h1 = __float2bfloat16_rn(v.y);
    __nv_bfloat16 h2 = __float2bfloat16_rn(v.z), h3 = __float2bfloat16_rn(v.w);
    __nv_bfloat16 l0 = __float2bfloat16_rn(v.x - __bfloat162float(h0));
    __nv_bfloat16 l1 = __float2bfloat16_rn(v.y - __bfloat162float(h1));
    __nv_bfloat16 l2 = __float2bfloat16_rn(v.z - __bfloat162float(h2));
    __nv_bfloat16 l3 = __float2bfloat16_rn(v.w - __bfloat162float(h3));
    H = make_uint2(pkbf2(h0, h1), pkbf2(h2, h3));
    L = make_uint2(pkbf2(l0, l1), pkbf2(l2, l3));
}

// ---------------- 1) embedding gather + bf16 split ----------------
__global__ __launch_bounds__(256) void gather_split(
    const int* __restrict__ tok, const float* __restrict__ emb,
    __nv_bfloat16* __restrict__ xhi, __nv_bfloat16* __restrict__ xlo)
{
    int id  = blockIdx.x * 256 + threadIdx.x;   // one float4 per thread
    int row = id >> 7;                          // 128 float4 per row
    int col = id & 127;
    int t   = tok[row];
    float4 v = reinterpret_cast<const float4*>(emb)[(size_t)t * 128 + col];
    uint2 H, L; split4(v, H, L);
    *reinterpret_cast<uint2*>(&xhi[(size_t)row * 512 + col * 4]) = H;
    *reinterpret_cast<uint2*>(&xlo[(size_t)row * 512 + col * 4]) = L;
}

// ---------------- 1b) weight split: 512x512 f32 -> bf16 hi/lo ----------------
__global__ __launch_bounds__(256) void wsplit(
    const float* __restrict__ w,
    __nv_bfloat16* __restrict__ whi, __nv_bfloat16* __restrict__ wlo)
{
    int i = blockIdx.x * 256 + threadIdx.x;     // 65536 float4
    float4 v = reinterpret_cast<const float4*>(w)[i];
    uint2 H, L; split4(v, H, L);
    *reinterpret_cast<uint2*>(&whi[(size_t)i * 4]) = H;
    *reinterpret_cast<uint2*>(&wlo[(size_t)i * 4]) = L;
}

// ---------------- 2) bf16-split tensor-core GEMM ----------------
// C[M,512] = A[M,512]·B[512,512]^T + bias1 + bias2  via  Ahi·Bhi + Ahi·Blo + Alo·Bhi
// CTA tile 128x256, 8 warps (2m x 4n) of 64x64; K chunks of 32, cp.async double buffer.
// smem rows padded to 80B (32 bf16 data + 16B) -> conflict-free b32 frag loads.
#define GM_THREADS 256
#define ST_A_LO    10240
#define ST_B_HI    20480
#define ST_B_OFF   20480   /* Blo - Bhi */
#define ST_SIZE    61440
#define GM_SMEM    (2*ST_SIZE + 1024)

__device__ __forceinline__ void gm_stage(
    int tid, int m0, int n0, int c, uint32_t sbase,
    const __nv_bfloat16* __restrict__ Ahi, const __nv_bfloat16* __restrict__ Alo,
    const __nv_bfloat16* __restrict__ Bhi, const __nv_bfloat16* __restrict__ Blo)
{
    const int k0 = c * 32;
    const uint32_t stg = sbase + (uint32_t)(c & 1) * ST_SIZE;
#pragma unroll
    for (int q = 0; q < 2; q++) {                 // A: 512 x 16B segs (hi), same lo
        int i = tid + q * 256;
        int row = i >> 2, sg = i & 3;
        uint32_t d = stg + (uint32_t)row * 80 + sg * 16;
        size_t s = (size_t)(m0 + row) * 512 + k0 + sg * 8;
        cpasync16(d, Ahi + s);
        cpasync16(d + ST_A_LO, Alo + s);
    }
#pragma unroll
    for (int q = 0; q < 4; q++) {                 // B: 1024 x 16B segs (hi), same lo
        int i = tid + q * 256;
        int row = i >> 2, sg = i & 3;
        uint32_t d = stg + ST_B_HI + (uint32_t)row * 80 + sg * 16;
        size_t s = (size_t)(n0 + row) * 512 + k0 + sg * 8;
        cpasync16(d, Bhi + s);
        cpasync16(d + ST_B_OFF, Blo + s);
    }
    asm volatile("cp.async.commit_group;" ::: "memory");
}

__global__ __launch_bounds__(GM_THREADS) void sgemm_mma(
    const __nv_bfloat16* __restrict__ Ahi, const __nv_bfloat16* __restrict__ Alo,
    const __nv_bfloat16* __restrict__ Bhi, const __nv_bfloat16* __restrict__ Blo,
    const float* __restrict__ bias1, const float* __restrict__ bias2,
    float* __restrict__ C)
{
    extern __shared__ char smem[];
    const uint32_t sbase = smem_u32(smem);
    float* bsum = reinterpret_cast<float*>(smem + 2 * ST_SIZE);

    const int tid  = threadIdx.x;
    const int lane = tid & 31;
    const int wid  = tid >> 5;
    const int wm = wid & 1, wn = wid >> 1;        // warp grid 2(m) x 4(n)
    const int g = lane >> 2, t = lane & 3;

    const int m0 = (blockIdx.x >> 1) * 128;
    const int n0 = (blockIdx.x & 1) * 256;

    bsum[tid] = bias1[n0 + tid] + bias2[n0 + tid];

    float acc[4][8][4];
#pragma unroll
    for (int mt = 0; mt < 4; mt++)
#pragma unroll
        for (int nt = 0; nt < 8; nt++)
#pragma unroll
            for (int r = 0; r < 4; r++) acc[mt][nt][r] = 0.f;

    gm_stage(tid, m0, n0, 0, sbase, Ahi, Alo, Bhi, Blo);

    for (int c = 0; c < 16; c++) {
        if (c + 1 < 16) {
            gm_stage(tid, m0, n0, c + 1, sbase, Ahi, Alo, Bhi, Blo);
            asm volatile("cp.async.wait_group 1;" ::: "memory");
        } else {
            asm volatile("cp.async.wait_group 0;" ::: "memory");
        }
        __syncthreads();

        const uint32_t stg = sbase + (uint32_t)(c & 1) * ST_SIZE;
#pragma unroll
        for (int kk = 0; kk < 2; kk++) {
            const uint32_t kb = kk * 32 + t * 4;     // byte offset of k-col 2t in this k16
            uint32_t bh[8][2], bl[8][2];
#pragma unroll
            for (int nt = 0; nt < 8; nt++) {
                uint32_t ab = stg + ST_B_HI + (uint32_t)(wn * 64 + nt * 8 + g) * 80 + kb;
                bh[nt][0] = lds32(ab);
                bh[nt][1] = lds32(ab + 16);
                bl[nt][0] = lds32(ab + ST_B_OFF);
                bl[nt][1] = lds32(ab + ST_B_OFF + 16);
            }
#pragma unroll
            for (int mt = 0; mt < 4; mt++) {
                uint32_t ar = stg + (uint32_t)(wm * 64 + mt * 16 + g) * 80 + kb;
                uint32_t ah0 = lds32(ar),           ah1 = lds32(ar + 8 * 80);
                uint32_t ah2 = lds32(ar + 16),      ah3 = lds32(ar + 8 * 80 + 16);
                uint32_t al0 = lds32(ar + ST_A_LO),      al1 = lds32(ar + ST_A_LO + 8 * 80);
                uint32_t al2 = lds32(ar + ST_A_LO + 16), al3 = lds32(ar + ST_A_LO + 8 * 80 + 16);
#pragma unroll
                for (int nt = 0; nt < 8; nt++)
                    mma16816(acc[mt][nt], ah0, ah1, ah2, ah3, bh[nt][0], bh[nt][1]);
#pragma unroll
                for (int nt = 0; nt < 8; nt++)
                    mma16816(acc[mt][nt], ah0, ah1, ah2, ah3, bl[nt][0], bl[nt][1]);
#pragma unroll
                for (int nt = 0; nt < 8; nt++)
                    mma16816(acc[mt][nt], al0, al1, al2, al3, bh[nt][0], bh[nt][1]);
            }
        }
        __syncthreads();
    }

    // epilogue: bias + store (c0,c1)->(row,col), (c2,c3)->(row+8,col)
#pragma unroll
    for (int mt = 0; mt < 4; mt++) {
        int row = m0 + wm * 64 + mt * 16 + g;
#pragma unroll
        for (int nt = 0; nt < 8; nt++) {
            int cl = wn * 64 + nt * 8 + 2 * t;
            float b0 = bsum[cl], b1 = bsum[cl + 1];
            float2 v0 = make_float2(acc[mt][nt][0] + b0, acc[mt][nt][1] + b1);
            float2 v1 = make_float2(acc[mt][nt][2] + b0, acc[mt][nt][3] + b1);
            *reinterpret_cast<float2*>(&C[(size_t)row * 512 + n0 + cl]) = v0;
            *reinterpret_cast<float2*>(&C[(size_t)(row + 8) * 512 + n0 + cl]) = v1;
        }
    }
}

// ---------------- 3) recurrent layer: one CTA per (dir, batch) ----------------
// h_t = tanh(xp_t + W_hh @ h_{t-1}).  (see R4 notes: k-packed f32x2, 24 reg rows + 8 smem rows)
// mode 0: output bf16 hi/lo split (feeds next GEMM); mode 1: output f32 with relu.
#define RNN_SMEM_FLOATS (512*32 + 256 + 8*264)
#define RNN_SMEM_BYTES  (RNN_SMEM_FLOATS * 4)

__global__ __launch_bounds__(512, 1) void rnn_layer(
    const float* __restrict__ xp,    // [B*T, 512]
    const float* __restrict__ Whh_l, // layer base: [2, 256, 256]
    float* __restrict__ xoutF,       // mode 1 target
    __nv_bfloat16* __restrict__ xoutH, __nv_bfloat16* __restrict__ xoutL, // mode 0
    int mode)
{
    extern __shared__ float sm[];
    float* Wsm = sm;                  // 512 threads x 32 floats, thread-private chunks
    float* hsm = sm + 512 * 32;       // plain h [256]
    float* P   = sm + 512 * 32 + 256; // partials [8][264]

    const int tid  = threadIdx.x;
    const int wid  = tid >> 5;
    const int lane = tid & 31;
    const int dir  = blockIdx.x >> 6;
    const int b    = blockIdx.x & 63;
    const float* W = Whh_l + (size_t)dir * HDIM * HDIM;   // [j][k] row-major

    const int s = tid >> 6;   // 0..7
    const int g = tid & 63;   // 0..63
    const int k0 = 32 * s;

    float4* WsmV = (float4*)Wsm;
#pragma unroll
    for (int cc = 0; cc < 8; cc++) {
        int jj = cc >> 1;
        int kb = 24 + 4 * (cc & 1);
        float4 w = *(const float4*)&W[(size_t)(4*g + jj) * HDIM + k0 + kb];
        WsmV[(wid * 8 + cc) * 32 + lane] = w;
    }

    unsigned long long wreg[12][4];
#pragma unroll
    for (int p = 0; p < 12; p++) {
#pragma unroll
        for (int jj = 0; jj < 4; jj++) {
            float2 w = *(const float2*)&W[(size_t)(4*g + jj) * HDIM + k0 + 2*p];
            wreg[p][jj] = pack2(w.x, w.y);
        }
    }

    if (tid < HDIM) hsm[tid] = 0.f;
    __syncthreads();

    const float* xpb = xp + (size_t)b * TLEN * EDIM + dir * HDIM;
    const size_t obase = (size_t)b * TLEN * EDIM + dir * HDIM;
    const int t0 = dir ? (TLEN - 1) : 0;
    const int dt = dir ? -1 : 1;

    float xp_cur = (tid < HDIM) ? xpb[(size_t)t0 * EDIM + tid] : 0.f;

    const ulonglong2* hp2 = (const ulonglong2*)(hsm + k0);
    const ulonglong2* wsv = (const ulonglong2*)Wsm + (wid * 8) * 32 + lane;

    int t = t0;
    for (int step = 0; step < TLEN; step++) {
        unsigned long long acc0 = 0ULL, acc1 = 0ULL, acc2 = 0ULL, acc3 = 0ULL;
#pragma unroll
        for (int c = 0; c < 6; c++) {
            ulonglong2 hp = hp2[c];
            fma2(acc0, wreg[2*c][0], hp.x);
            fma2(acc1, wreg[2*c][1], hp.x);
            fma2(acc2, wreg[2*c][2], hp.x);
            fma2(acc3, wreg[2*c][3], hp.x);
            fma2(acc0, wreg[2*c+1][0], hp.y);
            fma2(acc1, wreg[2*c+1][1], hp.y);
            fma2(acc2, wreg[2*c+1][2], hp.y);
            fma2(acc3, wreg[2*c+1][3], hp.y);
        }
        {
            ulonglong2 hp6 = hp2[6];
            ulonglong2 hp7 = hp2[7];
            ulonglong2 w;
            w = wsv[0*32]; fma2(acc0, w.x, hp6.x); fma2(acc0, w.y, hp6.y);
            w = wsv[1*32]; fma2(acc0, w.x, hp7.x); fma2(acc0, w.y, hp7.y);
            w = wsv[2*32]; fma2(acc1, w.x, hp6.x); fma2(acc1, w.y, hp6.y);
            w = wsv[3*32]; fma2(acc1, w.x, hp7.x); fma2(acc1, w.y, hp7.y);
            w = wsv[4*32]; fma2(acc2, w.x, hp6.x); fma2(acc2, w.y, hp6.y);
            w = wsv[5*32]; fma2(acc2, w.x, hp7.x); fma2(acc2, w.y, hp7.y);
            w = wsv[6*32]; fma2(acc3, w.x, hp6.x); fma2(acc3, w.y, hp6.y);
            w = wsv[7*32]; fma2(acc3, w.x, hp7.x); fma2(acc3, w.y, hp7.y);
        }

        float2 m0 = unpack2(acc0), m1 = unpack2(acc1), m2 = unpack2(acc2), m3 = unpack2(acc3);
        *(float4*)&P[s * 264 + 4 * g] =
            make_float4(m0.x + m0.y, m1.x + m1.y, m2.x + m2.y, m3.x + m3.y);
        __syncthreads();

        if (tid < HDIM) {
            float ssum = 0.f;
#pragma unroll
            for (int s2 = 0; s2 < 8; s2++) ssum += P[s2 * 264 + tid];
            float pre = ssum + xp_cur;
            if (step + 1 < TLEN)
                xp_cur = xpb[(size_t)(t + dt) * EDIM + tid];
            float hv = tanhf(pre);
            hsm[tid] = hv;
            if (mode) {
                xoutF[obase + (size_t)t * EDIM + tid] = fmaxf(hv, 0.f);
            } else {
                __nv_bfloat16 h = __float2bfloat16_rn(hv);
                xoutH[obase + (size_t)t * EDIM + tid] = h;
                xoutL[obase + (size_t)t * EDIM + tid] =
                    __float2bfloat16_rn(hv - __bfloat162float(h));
            }
        }
        __syncthreads();
        t += dt;
    }
}

// ---------------- 4) head input projection ----------------
__global__ __launch_bounds__(256) void head_proj(
    const float* __restrict__ x,
    const float* __restrict__ wi, const float* __restrict__ wf, const float* __restrict__ wc,
    const float* __restrict__ bii, const float* __restrict__ bhi,
    const float* __restrict__ bif, const float* __restrict__ bhf,
    const float* __restrict__ bic, const float* __restrict__ bhc,
    float* __restrict__ hxp)
{
    __shared__ float xs[16 * 516];
    int tid = threadIdx.x;
    int row0 = blockIdx.x * 16;

    for (int i = tid; i < 16 * 128; i += 256) {
        int r = i >> 7, c = i & 127;
        float4 v = reinterpret_cast<const float4*>(x + (size_t)(row0 + r) * 512)[c];
        *(float4*)&xs[r * 516 + c * 4] = v;
    }
    __syncthreads();

    int r = tid >> 4, c = tid & 15;
    if (c < 13) {
        const float* w;
        float bias;
        if (c < 3)      { w = wi + (size_t)c * 512;        bias = bii[c]     + bhi[c];     }
        else if (c < 8) { w = wf + (size_t)(c - 3) * 512;  bias = bif[c - 3] + bhf[c - 3]; }
        else            { w = wc + (size_t)(c - 8) * 512;  bias = bic[c - 8] + bhc[c - 8]; }
        float sum = 0.f;
        const float* xr = &xs[r * 516];
#pragma unroll 8
        for (int k = 0; k < 512; k += 4) {
            float4 wv = *(const float4*)&w[k];
            sum += xr[k] * wv.x + xr[k+1] * wv.y + xr[k+2] * wv.z + xr[k+3] * wv.w;
        }
        hxp[(size_t)(row0 + r) * 16 + c] = sum + bias;
    }
}

// ---------------- 5) head recurrences ----------------
__global__ __launch_bounds__(256) void head_rnn(
    const float* __restrict__ hxp,
    const float* __restrict__ whi, const float* __restrict__ whf, const float* __restrict__ whc,
    float* __restrict__ out)
{
    int wg   = (blockIdx.x * 256 + threadIdx.x) >> 5;   // 0..191
    int lane = threadIdx.x & 31;
    if (wg >= BATCH * 3) return;
    int b = wg / 3, head = wg - 3 * b;

    int C    = (head == 0) ? 3 : 5;
    int coff = (head == 0) ? 0 : ((head == 1) ? 3 : 8);
    const float* whh = (head == 0) ? whi : ((head == 1) ? whf : whc);
    size_t ooff = (head == 0) ? 0
                : ((head == 1) ? (size_t)NROWS * 3 : (size_t)NROWS * 8);

    float wr[5] = {0.f, 0.f, 0.f, 0.f, 0.f};
    if (lane < C) {
#pragma unroll
        for (int j = 0; j < 5; j++) if (j < C) wr[j] = whh[lane * C + j];
    }

    int xoffs = (lane < C) ? (coff + lane) : 0;
    const float* xb = hxp + (size_t)b * TLEN * 16 + xoffs;
    float*       ob = out + ooff + (size_t)b * TLEN * C + lane;

    float hv = 0.f;
    float Acur[8], Anxt[8];
#pragma unroll
    for (int i = 0; i < 8; i++) Acur[i] = xb[(size_t)i * 16];

    for (int tb = 0; tb < TLEN; tb += 8) {
        bool more = (tb + 8) < TLEN;
#pragma unroll
        for (int i = 0; i < 8; i++)
            Anxt[i] = more ? xb[(size_t)(tb + 8 + i) * 16] : 0.f;

#pragma unroll
        for (int i = 0; i < 8; i++) {
            float sum = Acur[i];
#pragma unroll
            for (int j = 0; j < 5; j++) {
                float hj = __shfl_sync(0xffffffffu, hv, j);
                sum += wr[j] * hj;
            }
            hv = tanhf(sum);
            if (lane < C) ob[(size_t)(tb + i) * C] = hv;
        }
#pragma unroll
        for (int i = 0; i < 8; i++) Acur[i] = Anxt[i];
    }
}

// ---------------- launch ----------------
extern "C" void kernel_launch(void* const* d_in, const int* in_sizes, int n_in,
                              void* d_out, int out_size)
{
    const int*   tokens = (const int*)  d_in[0];
    const float* emb    = (const float*)d_in[1];
    const float* w_ih   = (const float*)d_in[2];   // [2,2,256,512]
    const float* w_hh   = (const float*)d_in[3];   // [2,2,256,256]
    const float* b_ih   = (const float*)d_in[4];   // [2,2,256]
    const float* b_hh   = (const float*)d_in[5];
    const float* iwi = (const float*)d_in[6];
    const float* iwh = (const float*)d_in[7];
    const float* ibi = (const float*)d_in[8];
    const float* ibh = (const float*)d_in[9];
    const float* fwi = (const float*)d_in[10];
    const float* fwh = (const float*)d_in[11];
    const float* fbi = (const float*)d_in[12];
    const float* fbh = (const float*)d_in[13];
    const float* cwi = (const float*)d_in[14];
    const float* cwh = (const float*)d_in[15];
    const float* cbi = (const float*)d_in[16];
    const float* cbh = (const float*)d_in[17];
    float* out = (float*)d_out;

    float *px, *pxp, *phxp;
    __nv_bfloat16 *pahi, *palo, *pbhi, *pblo;
    cudaGetSymbolAddress((void**)&px,   g_x);
    cudaGetSymbolAddress((void**)&pxp,  g_xp);
    cudaGetSymbolAddress((void**)&phxp, g_hxp);
    cudaGetSymbolAddress((void**)&pahi, g_ahi);
    cudaGetSymbolAddress((void**)&palo, g_alo);
    cudaGetSymbolAddress((void**)&pbhi, g_bhi);
    cudaGetSymbolAddress((void**)&pblo, g_blo);

    cudaFuncSetAttribute(rnn_layer, cudaFuncAttributeMaxDynamicSharedMemorySize, RNN_SMEM_BYTES);
    cudaFuncSetAttribute(sgemm_mma, cudaFuncAttributeMaxDynamicSharedMemorySize, GM_SMEM);

    // layer 0
    wsplit<<<256, 256>>>(w_ih, pbhi, pblo);
    gather_split<<<(NROWS * 128) / 256, 256>>>(tokens, emb, pahi, palo);
    sgemm_mma<<<1024, GM_THREADS, GM_SMEM>>>(pahi, palo, pbhi, pblo, b_ih, b_hh, pxp);
    rnn_layer<<<128, 512, RNN_SMEM_BYTES>>>(pxp, w_hh, nullptr, pahi, palo, 0);

    // layer 1 (relu fused into rnn output)
    wsplit<<<256, 256>>>(w_ih + (size_t)2 * HDIM * EDIM, pbhi, pblo);
    sgemm_mma<<<1024, GM_THREADS, GM_SMEM>>>(pahi, palo, pbhi, pblo,
                                             b_ih + 2 * HDIM, b_hh + 2 * HDIM, pxp);
    rnn_layer<<<128, 512, RNN_SMEM_BYTES>>>(pxp, w_hh + (size_t)2 * HDIM * HDIM,
                                            px, nullptr, nullptr, 1);

    // heads
    head_proj<<<NROWS / 16, 256>>>(px, iwi, fwi, cwi, ibi, ibh, fbi, fbh, cbi, cbh, phxp);
    head_rnn<<<24, 256>>>(phxp, iwh, fwh, cwh, out);
}